// round 9
// baseline (speedup 1.0000x reference)
#include <cuda_runtime.h>
#include <cooperative_groups.h>
#include <cstdint>

namespace cg = cooperative_groups;

#define T_STEPS 512
#define BATCH   256
#define IN0     128
#define HID     256
#define G3      768   // 3*HID

// ---------------- scratch (static device arrays; allocation-free) ------------
__device__ float g_gi[(size_t)T_STEPS * BATCH * G3];   // reused by both layers
__device__ float g_h1[(size_t)T_STEPS * BATCH * HID];  // layer-0 outputs
__device__ float g_h2[BATCH * HID];                    // final hidden state

// ======================= helpers ========================
__device__ __forceinline__ float f2tf32(float x) {
    float r;
    asm("cvt.rna.tf32.f32 %0, %1;" : "=f"(r) : "f"(x));
    return r;
}

__device__ __forceinline__ void mma_tf32(float* d, const float* a, const float* b) {
    asm volatile(
        "mma.sync.aligned.m16n8k8.row.col.f32.tf32.tf32.f32 "
        "{%0,%1,%2,%3}, {%4,%5,%6,%7}, {%8,%9}, {%0,%1,%2,%3};"
        : "+f"(d[0]), "+f"(d[1]), "+f"(d[2]), "+f"(d[3])
        : "r"(__float_as_uint(a[0])), "r"(__float_as_uint(a[1])),
          "r"(__float_as_uint(a[2])), "r"(__float_as_uint(a[3])),
          "r"(__float_as_uint(b[0])), "r"(__float_as_uint(b[1])));
}

__device__ __forceinline__ void cp_async16(uint32_t dst, const void* src) {
    asm volatile("cp.async.cg.shared.global [%0], [%1], 16;"
                 :: "r"(dst), "l"(src) : "memory");
}

__device__ __forceinline__ float tanh_fast(float x) {
    float r;
    asm("tanh.approx.f32 %0, %1;" : "=f"(r) : "f"(x));
    return r;
}

#define MBAR_INIT(addr, cnt) \
    asm volatile("mbarrier.init.shared.b64 [%0], %1;" \
                 :: "r"((uint32_t)(addr)), "r"((uint32_t)(cnt)) : "memory")

// arrive (release, cluster scope) on rank rk's mbarrier at the same smem offset
#define MBAR_ARRIVE_RANK(local_addr, rk)                                        \
    asm volatile("{\n\t.reg .b32 ra;\n\t"                                       \
        "mapa.shared::cluster.u32 ra, %0, %1;\n\t"                              \
        "mbarrier.arrive.release.cluster.shared::cluster.b64 _, [ra];\n\t}"     \
        :: "r"((uint32_t)(local_addr)), "r"((uint32_t)(rk)) : "memory")

#define MBAR_WAIT(addr, par) do {                                               \
    uint32_t _m = (uint32_t)(addr); uint32_t _p = (uint32_t)(par); uint32_t _d; \
    asm volatile("{\n\t.reg .pred p;\n\t"                                       \
        "mbarrier.try_wait.parity.acquire.cluster.shared::cta.b64 p, [%1], %2;\n\t" \
        "selp.b32 %0, 1, 0, p;\n\t}"                                            \
        : "=r"(_d) : "r"(_m), "r"(_p) : "memory");                              \
    if (!_d) {                                                                  \
        asm volatile("{\n\t.reg .pred P1;\n\t"                                  \
            "WL_%=:\n\t"                                                        \
            "mbarrier.try_wait.parity.acquire.cluster.shared::cta.b64 P1, [%0], %1, 0x989680;\n\t" \
            "@P1 bra.uni WD_%=;\n\t"                                            \
            "bra.uni WL_%=;\n\t"                                                \
            "WD_%=:\n\t}"                                                       \
            :: "r"(_m), "r"(_p) : "memory");                                    \
    }                                                                           \
} while (0)

// =============================================================================
// HMMA tf32 GEMM:  C[M,N] = A[M,K] @ Bw[N,K]^T + bias[N]   (validated R4)
// =============================================================================
#define PITCH 136

__global__ __launch_bounds__(256, 2) void gemm_tf32mma(
    const float* __restrict__ A, const float* __restrict__ Bw,
    const float* __restrict__ bias, float* __restrict__ C,
    int N, int K)
{
    __shared__ float As[2][16][PITCH];
    __shared__ float Bs[2][16][PITCH];

    const int t    = threadIdx.x;
    const int bx   = blockIdx.x;
    const int by   = blockIdx.y;
    const int lane = t & 31;
    const int w    = t >> 5;
    const int wm   = w & 3;
    const int wn   = w >> 2;
    const int gid  = lane >> 2;
    const int tig  = lane & 3;

    const float* Ab = A  + (size_t)(by * 128) * K;
    const float* Bb = Bw + (size_t)(bx * 128) * K;

    const int lm = t & 127;
    const int f0 = (t >> 7) * 2;

    float acc[2][8][4];
#pragma unroll
    for (int i = 0; i < 2; i++)
#pragma unroll
        for (int jx = 0; jx < 8; jx++)
#pragma unroll
            for (int q = 0; q < 4; q++) acc[i][jx][q] = 0.0f;

    float4 pa[2], pb[2];
#pragma unroll
    for (int r = 0; r < 2; r++) {
        pa[r] = *(const float4*)(Ab + (size_t)lm * K + (f0 + r) * 4);
        pb[r] = *(const float4*)(Bb + (size_t)lm * K + (f0 + r) * 4);
    }
#pragma unroll
    for (int r = 0; r < 2; r++) {
        const int kk = (f0 + r) * 4;
        As[0][kk + 0][lm] = f2tf32(pa[r].x);
        As[0][kk + 1][lm] = f2tf32(pa[r].y);
        As[0][kk + 2][lm] = f2tf32(pa[r].z);
        As[0][kk + 3][lm] = f2tf32(pa[r].w);
        Bs[0][kk + 0][lm] = f2tf32(pb[r].x);
        Bs[0][kk + 1][lm] = f2tf32(pb[r].y);
        Bs[0][kk + 2][lm] = f2tf32(pb[r].z);
        Bs[0][kk + 3][lm] = f2tf32(pb[r].w);
    }
    __syncthreads();

    const int nst = K >> 4;
    for (int s = 0; s < nst; s++) {
        const int cur = s & 1;
        const bool pf = (s + 1 < nst);
        if (pf) {
            const int kbase = (s + 1) * 16;
#pragma unroll
            for (int r = 0; r < 2; r++) {
                pa[r] = *(const float4*)(Ab + (size_t)lm * K + kbase + (f0 + r) * 4);
                pb[r] = *(const float4*)(Bb + (size_t)lm * K + kbase + (f0 + r) * 4);
            }
        }
#pragma unroll
        for (int kk = 0; kk < 16; kk += 8) {
            float a[2][4], b[8][2];
#pragma unroll
            for (int i = 0; i < 2; i++) {
                const int m = wm * 32 + i * 16 + gid;
                a[i][0] = As[cur][kk + tig][m];
                a[i][1] = As[cur][kk + tig][m + 8];
                a[i][2] = As[cur][kk + tig + 4][m];
                a[i][3] = As[cur][kk + tig + 4][m + 8];
            }
#pragma unroll
            for (int jx = 0; jx < 8; jx++) {
                const int n = wn * 64 + jx * 8 + gid;
                b[jx][0] = Bs[cur][kk + tig][n];
                b[jx][1] = Bs[cur][kk + tig + 4][n];
            }
#pragma unroll
            for (int i = 0; i < 2; i++)
#pragma unroll
                for (int jx = 0; jx < 8; jx++)
                    mma_tf32(acc[i][jx], a[i], b[jx]);
        }
        if (pf) {
            const int nxt = cur ^ 1;
#pragma unroll
            for (int r = 0; r < 2; r++) {
                const int kk = (f0 + r) * 4;
                As[nxt][kk + 0][lm] = f2tf32(pa[r].x);
                As[nxt][kk + 1][lm] = f2tf32(pa[r].y);
                As[nxt][kk + 2][lm] = f2tf32(pa[r].z);
                As[nxt][kk + 3][lm] = f2tf32(pa[r].w);
                Bs[nxt][kk + 0][lm] = f2tf32(pb[r].x);
                Bs[nxt][kk + 1][lm] = f2tf32(pb[r].y);
                Bs[nxt][kk + 2][lm] = f2tf32(pb[r].z);
                Bs[nxt][kk + 3][lm] = f2tf32(pb[r].w);
            }
        }
        __syncthreads();
    }

#pragma unroll
    for (int i = 0; i < 2; i++) {
        const int m0 = by * 128 + wm * 32 + i * 16 + gid;
#pragma unroll
        for (int jx = 0; jx < 8; jx++) {
            const int n = bx * 128 + wn * 64 + jx * 8 + tig * 2;
            const float b0 = __ldg(bias + n);
            const float b1 = __ldg(bias + n + 1);
            float2 v0, v1;
            v0.x = acc[i][jx][0] + b0;  v0.y = acc[i][jx][1] + b1;
            v1.x = acc[i][jx][2] + b0;  v1.y = acc[i][jx][3] + b1;
            *(float2*)(C + (size_t)m0 * N + n)       = v0;
            *(float2*)(C + (size_t)(m0 + 8) * N + n) = v1;
        }
    }
}

// =============================================================================
// HMMA persistent GRU recurrence, v3c: two pipelined batch groups per cluster.
// 16 clusters x 4 CTAs; cluster owns 16 batch rows (g0: 8, g1: 8).
// v3c fix: cp.async.wait_group is PER-THREAD -> must be executed by ALL
// threads BEFORE the __syncthreads that precedes gates (round-8 race: gates
// threads read gi_s chunks copied by other threads whose copies hadn't landed).
// =============================================================================
#define HP 9
// smem float offsets
#define OFF_HBUF(g, par) (((g) * 2 + (par)) * (256 * HP))
#define OFF_GH(g)        (4 * 256 * HP + (g) * 1600)
#define OFF_GIS(g, par)  (4 * 256 * HP + 3200 + ((g) * 2 + (par)) * 1536)
#define OFF_BHH          (4 * 256 * HP + 3200 + 4 * 1536)
#define OFF_MBAR         (OFF_BHH + 192)          // 2 x u64 (8-byte aligned)
#define REC_SMEM_BYTES   ((OFF_MBAR + 4) * 4)

#define GEMM_PHASE(HRD, GHP) do {                                         \
    float c0[4] = {0, 0, 0, 0}, c1[4] = {0, 0, 0, 0};                     \
    const float* hb_ = (HRD) + tig * HP + gid;                            \
    _Pragma("unroll")                                                     \
    for (int s = 0; s < 32; s += 2) {                                     \
        float b0_[2] = { hb_[(s + 0) * 8 * HP], hb_[(s + 0) * 8 * HP + 4 * HP] }; \
        float b1_[2] = { hb_[(s + 1) * 8 * HP], hb_[(s + 1) * 8 * HP + 4 * HP] }; \
        float w0_[4] = { wa0[s], wa1[s], wa2[s], wa3[s] };                \
        float w1_[4] = { wa0[s + 1], wa1[s + 1], wa2[s + 1], wa3[s + 1] };\
        mma_tf32(c0, w0_, b0_);                                           \
        mma_tf32(c1, w1_, b1_);                                           \
    }                                                                     \
    const int lr_ = w * 16 + gid;                                         \
    const int bi_ = tig * 2;                                              \
    (GHP)[(bi_    ) * 200 + lr_    ] = c0[0] + c1[0];                     \
    (GHP)[(bi_ + 1) * 200 + lr_    ] = c0[1] + c1[1];                     \
    (GHP)[(bi_    ) * 200 + lr_ + 8] = c0[2] + c1[2];                     \
    (GHP)[(bi_ + 1) * 200 + lr_ + 8] = c0[3] + c1[3];                     \
} while (0)

#define GATES_PHASE(GHP, GISP, HWR, HPA, HPB, BB0) do {                   \
    const float br_ = bhh[j], bz_ = bhh[64 + j], bn_ = bhh[128 + j];      \
    _Pragma("unroll")                                                     \
    for (int i_ = 0; i_ < 2; i_++) {                                      \
        const int b_ = bb + 4 * i_;                                       \
        const float hr_ = (GHP)[b_ * 200 + j]       + br_;                \
        const float hz_ = (GHP)[b_ * 200 + 64 + j]  + bz_;                \
        const float hn_ = (GHP)[b_ * 200 + 128 + j] + bn_;                \
        const float ir_  = (GISP)[b_ * 192 + j];                          \
        const float iz_  = (GISP)[b_ * 192 + 64 + j];                     \
        const float in2_ = (GISP)[b_ * 192 + 128 + j];                    \
        const float r_ = __fdividef(1.0f, 1.0f + __expf(-(ir_ + hr_)));   \
        const float z_ = __fdividef(1.0f, 1.0f + __expf(-(iz_ + hz_)));   \
        const float n_ = tanh_fast(in2_ + r_ * hn_);                      \
        const float hp_ = (i_ == 0) ? (HPA) : (HPB);                      \
        const float hv_ = (1.0f - z_) * n_ + z_ * hp_;                    \
        if (i_ == 0) (HPA) = hv_; else (HPB) = hv_;                       \
        const float ho_ = f2tf32(hv_);                                    \
        float* lp_ = (HWR) + kglob * HP + b_;                             \
        _Pragma("unroll")                                                 \
        for (int q_ = 0; q_ < 4; q_++)                                    \
            *(float*)cluster.map_shared_rank(lp_, q_) = ho_;              \
        if (store_all) {                                                  \
            hout[((size_t)ts * BATCH + (BB0) + b_) * HID + kglob] = hv_;  \
        } else if (ts == T_STEPS - 1) {                                   \
            hout[(size_t)((BB0) + b_) * HID + kglob] = hv_;               \
        }                                                                 \
    }                                                                     \
} while (0)

__global__ void __cluster_dims__(4, 1, 1) __launch_bounds__(384, 1)
gru_rec_mma(const float* __restrict__ Whh, const float* __restrict__ bhh_g,
            const float* __restrict__ gi, float* __restrict__ hout,
            int store_all)
{
    extern __shared__ float smf[];
    float* bhh = smf + OFF_BHH;
    const uint32_t mbar0 = (uint32_t)__cvta_generic_to_shared(smf + OFF_MBAR);
    const uint32_t mbar1 = mbar0 + 8;

    cg::cluster_group cluster = cg::this_cluster();
    const int rank = cluster.block_rank();
    const int B0   = (blockIdx.x >> 2) * 16;       // 16 batch rows per cluster

    const int t    = threadIdx.x;
    const int lane = t & 31;
    const int w    = t >> 5;              // 0..11
    const int gid  = lane >> 2;           // 0..7
    const int tig  = lane & 3;            // 0..3

    // ---- W_hh fragments -> registers (once): warp w owns m-tile w ----
    float wa0[32], wa1[32], wa2[32], wa3[32];
    {
        const int g  = w >> 2;
        const int r0 = g * 256 + rank * 64 + (w & 3) * 16 + gid;
        const float* p0 = Whh + (size_t)r0 * 256;
        const float* p1 = p0 + 8 * 256;
#pragma unroll
        for (int s = 0; s < 32; s++) {
            wa0[s] = f2tf32(p0[8 * s + tig]);
            wa1[s] = f2tf32(p1[8 * s + tig]);
            wa2[s] = f2tf32(p0[8 * s + tig + 4]);
            wa3[s] = f2tf32(p1[8 * s + tig + 4]);
        }
    }
    for (int i = t; i < 192; i += 384)
        bhh[i] = bhh_g[((i >> 6) << 8) + rank * 64 + (i & 63)];
    for (int i = t; i < 4 * 256 * HP; i += 384) smf[i] = 0.0f;   // zero all hbufs
    if (t == 0) { MBAR_INIT(mbar0, 4); MBAR_INIT(mbar1, 4); }
    __syncthreads();
    cluster.sync();                         // mbars + zeroed hbufs visible
    if (t < 4) MBAR_ARRIVE_RANK(mbar0, t);  // prime mbar0 phase 0 (h0(0) ready)

    // gate-phase identity (threads 0..255)
    const int j     = t & 63;
    const int bb    = (t >> 6) & 3;
    const int kglob = rank * 64 + j;
    float h0a = 0.0f, h0b = 0.0f;           // exact fp32 state, group 0
    float h1a = 0.0f, h1b = 0.0f;           // exact fp32 state, group 1

    // cp.async chunk identity (all 384 threads, 16B each per group)
    const int cb   = t / 48;
    const int crem = t % 48;
    const int cg_  = crem >> 4;
    const int cq   = crem & 15;
    const uint32_t gis0_dst = (uint32_t)__cvta_generic_to_shared(
        smf + OFF_GIS(0, 0) + cb * 192 + cg_ * 64 + cq * 4);
    const uint32_t gis1_dst = gis0_dst + (uint32_t)(OFF_GIS(1, 0) - OFF_GIS(0, 0)) * 4;
    const float* gi_src0 = gi + ((size_t)B0 + cb) * G3 + cg_ * 256 + rank * 64 + cq * 4;
    const float* gi_src1 = gi_src0 + (size_t)8 * G3;

    float* gh0 = smf + OFF_GH(0);
    float* gh1 = smf + OFF_GH(1);

    for (int ts = 0; ts < T_STEPS; ts++) {
        const int par = ts & 1;
        const size_t goff = (size_t)ts * BATCH * G3;

        // prefetch this step's gi for both groups (parity-buffered)
        cp_async16(gis0_dst + par * 1536 * 4, gi_src0 + goff);
        asm volatile("cp.async.commit_group;" ::: "memory");
        cp_async16(gis1_dst + par * 1536 * 4, gi_src1 + goff);
        asm volatile("cp.async.commit_group;" ::: "memory");

        // ================= group 0 =================
        MBAR_WAIT(mbar0, par);                         // h0(ts) visible
        GEMM_PHASE(smf + OFF_HBUF(0, par), gh0);
        // per-thread wait for OWN gis0 copy BEFORE the barrier -> after the
        // barrier, every thread's gis0 chunk is visible to all (v3c fix)
        asm volatile("cp.async.wait_group 1;" ::: "memory");
        __syncthreads();                               // gh0 + gis0 ready
        if (t < 4) MBAR_ARRIVE_RANK(mbar1, t);         // signal h1(ts)
        if (t < 256) {
            GATES_PHASE(gh0, smf + OFF_GIS(0, par), smf + OFF_HBUF(0, par ^ 1),
                        h0a, h0b, B0);
        }

        // ================= group 1 =================
        MBAR_WAIT(mbar1, par);                         // h1(ts) visible
        GEMM_PHASE(smf + OFF_HBUF(1, par), gh1);
        asm volatile("cp.async.wait_group 0;" ::: "memory");   // (v3c fix)
        __syncthreads();                               // gh1 + gis1 ready
        if (t < 4) MBAR_ARRIVE_RANK(mbar0, t);         // signal h0(ts+1)
        if (t < 256) {
            GATES_PHASE(gh1, smf + OFF_GIS(1, par), smf + OFF_HBUF(1, par ^ 1),
                        h1a, h1b, B0 + 8);
        }
    }

    // REQUIRED: no CTA may exit while peers can still DSMEM-store into its
    // SMEM (final step's gates writes).
    cluster.sync();
}

// =============================================================================
// FC on the last hidden state
// =============================================================================
__global__ __launch_bounds__(256) void fc_kernel(
    const float* __restrict__ Wfc, const float* __restrict__ bfc,
    float* __restrict__ out)
{
    __shared__ float hs[256];
    const int b = blockIdx.x;
    const int o = threadIdx.x;
    hs[o] = g_h2[b * 256 + o];
    __syncthreads();
    const float* wr = Wfc + (size_t)o * 256;
    float acc = 0.0f;
#pragma unroll 8
    for (int k = 0; k < 256; k += 4) {
        const float4 wv = *(const float4*)(wr + k);
        acc += hs[k] * wv.x + hs[k + 1] * wv.y + hs[k + 2] * wv.z + hs[k + 3] * wv.w;
    }
    out[b * 256 + o] = acc + bfc[o];
}

// =============================================================================
extern "C" void kernel_launch(void* const* d_in, const int* in_sizes, int n_in,
                              void* d_out, int out_size)
{
    const float* x     = (const float*)d_in[0];
    const float* W_ih0 = (const float*)d_in[1];
    const float* W_hh0 = (const float*)d_in[2];
    const float* b_ih0 = (const float*)d_in[3];
    const float* b_hh0 = (const float*)d_in[4];
    const float* W_ih1 = (const float*)d_in[5];
    const float* W_hh1 = (const float*)d_in[6];
    const float* b_ih1 = (const float*)d_in[7];
    const float* b_hh1 = (const float*)d_in[8];
    const float* W_fc  = (const float*)d_in[9];
    const float* b_fc  = (const float*)d_in[10];
    float* out = (float*)d_out;

    float *gi_p, *h1_p, *h2_p;
    cudaGetSymbolAddress((void**)&gi_p, g_gi);
    cudaGetSymbolAddress((void**)&h1_p, g_h1);
    cudaGetSymbolAddress((void**)&h2_p, g_h2);

    cudaFuncSetAttribute(gru_rec_mma, cudaFuncAttributeMaxDynamicSharedMemorySize,
                         REC_SMEM_BYTES);

    const int M = T_STEPS * BATCH;        // 131072
    dim3 gemm_grid(G3 / 128, M / 128);    // (6, 1024)

    // layer 0: gi0 = x @ W_ih0^T + b_ih0   (tf32 HMMA, K=128)
    gemm_tf32mma<<<gemm_grid, 256>>>(x, W_ih0, b_ih0, gi_p, G3, IN0);
    // layer 0 recurrence -> g_h1[T,B,H]   (16 clusters x 4 CTAs, 16 batch each)
    gru_rec_mma<<<64, 384, REC_SMEM_BYTES>>>(W_hh0, b_hh0, gi_p, h1_p, 1);
    // layer 1: gi1 = h1 @ W_ih1^T + b_ih1  (tf32 HMMA, K=256)
    gemm_tf32mma<<<gemm_grid, 256>>>(h1_p, W_ih1, b_ih1, gi_p, G3, HID);
    // layer 1 recurrence -> g_h2[B,H]
    gru_rec_mma<<<64, 384, REC_SMEM_BYTES>>>(W_hh1, b_hh1, gi_p, h2_p, 0);
    // FC head
    fc_kernel<<<BATCH, 256>>>(W_fc, b_fc, out);
}

// round 10
// speedup vs baseline: 1.3625x; 1.3625x over previous
#include <cuda_runtime.h>
#include <cooperative_groups.h>
#include <cstdint>

namespace cg = cooperative_groups;

#define T_STEPS 512
#define BATCH   256
#define IN0     128
#define HID     256
#define G3      768   // 3*HID

// ---------------- scratch (static device arrays; allocation-free) ------------
__device__ float g_gi[(size_t)T_STEPS * BATCH * G3];   // reused by both layers
__device__ float g_h1[(size_t)T_STEPS * BATCH * HID];  // layer-0 outputs
__device__ float g_h2[BATCH * HID];                    // final hidden state

// ======================= helpers ========================
__device__ __forceinline__ float f2tf32(float x) {
    float r;
    asm("cvt.rna.tf32.f32 %0, %1;" : "=f"(r) : "f"(x));
    return r;
}

__device__ __forceinline__ void mma_tf32(float* d, const float* a, const float* b) {
    asm volatile(
        "mma.sync.aligned.m16n8k8.row.col.f32.tf32.tf32.f32 "
        "{%0,%1,%2,%3}, {%4,%5,%6,%7}, {%8,%9}, {%0,%1,%2,%3};"
        : "+f"(d[0]), "+f"(d[1]), "+f"(d[2]), "+f"(d[3])
        : "r"(__float_as_uint(a[0])), "r"(__float_as_uint(a[1])),
          "r"(__float_as_uint(a[2])), "r"(__float_as_uint(a[3])),
          "r"(__float_as_uint(b[0])), "r"(__float_as_uint(b[1])));
}

__device__ __forceinline__ void cp_async16(uint32_t dst, const void* src) {
    asm volatile("cp.async.cg.shared.global [%0], [%1], 16;"
                 :: "r"(dst), "l"(src) : "memory");
}

__device__ __forceinline__ float tanh_fast(float x) {
    float r;
    asm("tanh.approx.f32 %0, %1;" : "=f"(r) : "f"(x));
    return r;
}

#define MBAR_INIT(addr, cnt) \
    asm volatile("mbarrier.init.shared.b64 [%0], %1;" \
                 :: "r"((uint32_t)(addr)), "r"((uint32_t)(cnt)) : "memory")

// arrive (release, cluster scope) on rank rk's mbarrier at the same smem offset
#define MBAR_ARRIVE_RANK(local_addr, rk)                                        \
    asm volatile("{\n\t.reg .b32 ra;\n\t"                                       \
        "mapa.shared::cluster.u32 ra, %0, %1;\n\t"                              \
        "mbarrier.arrive.release.cluster.shared::cluster.b64 _, [ra];\n\t}"     \
        :: "r"((uint32_t)(local_addr)), "r"((uint32_t)(rk)) : "memory")

#define MBAR_WAIT(addr, par) do {                                               \
    uint32_t _m = (uint32_t)(addr); uint32_t _p = (uint32_t)(par); uint32_t _d; \
    asm volatile("{\n\t.reg .pred p;\n\t"                                       \
        "mbarrier.try_wait.parity.acquire.cluster.shared::cta.b64 p, [%1], %2;\n\t" \
        "selp.b32 %0, 1, 0, p;\n\t}"                                            \
        : "=r"(_d) : "r"(_m), "r"(_p) : "memory");                              \
    if (!_d) {                                                                  \
        asm volatile("{\n\t.reg .pred P1;\n\t"                                  \
            "WL_%=:\n\t"                                                        \
            "mbarrier.try_wait.parity.acquire.cluster.shared::cta.b64 P1, [%0], %1, 0x989680;\n\t" \
            "@P1 bra.uni WD_%=;\n\t"                                            \
            "bra.uni WL_%=;\n\t"                                                \
            "WD_%=:\n\t}"                                                       \
            :: "r"(_m), "r"(_p) : "memory");                                    \
    }                                                                           \
} while (0)

// =============================================================================
// HMMA tf32 GEMM:  C[M,N] = A[M,K] @ Bw[N,K]^T + bias[N]   (validated R4)
// =============================================================================
#define PITCH 136

__global__ __launch_bounds__(256, 2) void gemm_tf32mma(
    const float* __restrict__ A, const float* __restrict__ Bw,
    const float* __restrict__ bias, float* __restrict__ C,
    int N, int K)
{
    __shared__ float As[2][16][PITCH];
    __shared__ float Bs[2][16][PITCH];

    const int t    = threadIdx.x;
    const int bx   = blockIdx.x;
    const int by   = blockIdx.y;
    const int lane = t & 31;
    const int w    = t >> 5;
    const int wm   = w & 3;
    const int wn   = w >> 2;
    const int gid  = lane >> 2;
    const int tig  = lane & 3;

    const float* Ab = A  + (size_t)(by * 128) * K;
    const float* Bb = Bw + (size_t)(bx * 128) * K;

    const int lm = t & 127;
    const int f0 = (t >> 7) * 2;

    float acc[2][8][4];
#pragma unroll
    for (int i = 0; i < 2; i++)
#pragma unroll
        for (int jx = 0; jx < 8; jx++)
#pragma unroll
            for (int q = 0; q < 4; q++) acc[i][jx][q] = 0.0f;

    float4 pa[2], pb[2];
#pragma unroll
    for (int r = 0; r < 2; r++) {
        pa[r] = *(const float4*)(Ab + (size_t)lm * K + (f0 + r) * 4);
        pb[r] = *(const float4*)(Bb + (size_t)lm * K + (f0 + r) * 4);
    }
#pragma unroll
    for (int r = 0; r < 2; r++) {
        const int kk = (f0 + r) * 4;
        As[0][kk + 0][lm] = f2tf32(pa[r].x);
        As[0][kk + 1][lm] = f2tf32(pa[r].y);
        As[0][kk + 2][lm] = f2tf32(pa[r].z);
        As[0][kk + 3][lm] = f2tf32(pa[r].w);
        Bs[0][kk + 0][lm] = f2tf32(pb[r].x);
        Bs[0][kk + 1][lm] = f2tf32(pb[r].y);
        Bs[0][kk + 2][lm] = f2tf32(pb[r].z);
        Bs[0][kk + 3][lm] = f2tf32(pb[r].w);
    }
    __syncthreads();

    const int nst = K >> 4;
    for (int s = 0; s < nst; s++) {
        const int cur = s & 1;
        const bool pf = (s + 1 < nst);
        if (pf) {
            const int kbase = (s + 1) * 16;
#pragma unroll
            for (int r = 0; r < 2; r++) {
                pa[r] = *(const float4*)(Ab + (size_t)lm * K + kbase + (f0 + r) * 4);
                pb[r] = *(const float4*)(Bb + (size_t)lm * K + kbase + (f0 + r) * 4);
            }
        }
#pragma unroll
        for (int kk = 0; kk < 16; kk += 8) {
            float a[2][4], b[8][2];
#pragma unroll
            for (int i = 0; i < 2; i++) {
                const int m = wm * 32 + i * 16 + gid;
                a[i][0] = As[cur][kk + tig][m];
                a[i][1] = As[cur][kk + tig][m + 8];
                a[i][2] = As[cur][kk + tig + 4][m];
                a[i][3] = As[cur][kk + tig + 4][m + 8];
            }
#pragma unroll
            for (int jx = 0; jx < 8; jx++) {
                const int n = wn * 64 + jx * 8 + gid;
                b[jx][0] = Bs[cur][kk + tig][n];
                b[jx][1] = Bs[cur][kk + tig + 4][n];
            }
#pragma unroll
            for (int i = 0; i < 2; i++)
#pragma unroll
                for (int jx = 0; jx < 8; jx++)
                    mma_tf32(acc[i][jx], a[i], b[jx]);
        }
        if (pf) {
            const int nxt = cur ^ 1;
#pragma unroll
            for (int r = 0; r < 2; r++) {
                const int kk = (f0 + r) * 4;
                As[nxt][kk + 0][lm] = f2tf32(pa[r].x);
                As[nxt][kk + 1][lm] = f2tf32(pa[r].y);
                As[nxt][kk + 2][lm] = f2tf32(pa[r].z);
                As[nxt][kk + 3][lm] = f2tf32(pa[r].w);
                Bs[nxt][kk + 0][lm] = f2tf32(pb[r].x);
                Bs[nxt][kk + 1][lm] = f2tf32(pb[r].y);
                Bs[nxt][kk + 2][lm] = f2tf32(pb[r].z);
                Bs[nxt][kk + 3][lm] = f2tf32(pb[r].w);
            }
        }
        __syncthreads();
    }

#pragma unroll
    for (int i = 0; i < 2; i++) {
        const int m0 = by * 128 + wm * 32 + i * 16 + gid;
#pragma unroll
        for (int jx = 0; jx < 8; jx++) {
            const int n = bx * 128 + wn * 64 + jx * 8 + tig * 2;
            const float b0 = __ldg(bias + n);
            const float b1 = __ldg(bias + n + 1);
            float2 v0, v1;
            v0.x = acc[i][jx][0] + b0;  v0.y = acc[i][jx][1] + b1;
            v1.x = acc[i][jx][2] + b0;  v1.y = acc[i][jx][3] + b1;
            *(float2*)(C + (size_t)m0 * N + n)       = v0;
            *(float2*)(C + (size_t)(m0 + 8) * N + n) = v1;
        }
    }
}

// =============================================================================
// HMMA persistent GRU recurrence, v4:
//  Round-6 geometry (32 clusters x 4 CTAs, 8 batch/cluster, grid 128 -> 128 SMs
//  busy, best measured per-step), with:
//   - per-step cluster.sync -> mbarrier arrive/wait (no CCTL.IVALL L1 flush,
//     ~60-90cyc wait vs ~490) using the round-9-validated ordering
//     (stores -> bar.sync -> t<4 release-arrive on all 4 ranks).
//   - gi prefetched ONE STEP AHEAD (double-buffered gi_s, wait_group 1) so
//     cp.async has a full step of latency cover.
//   - 4 independent MMA accumulator chains (depth 8, as round 6).
//  Numerics identical to round 6 (rel_err 3.04e-4).
// =============================================================================
#define HP 9
#define OFF_HBUF(par) ((par) * (256 * HP))
#define OFF_GH        (2 * 256 * HP)                    // 4608
#define OFF_GIS(par)  (2 * 256 * HP + 1600 + (par) * 1536)
#define OFF_BHH       (2 * 256 * HP + 1600 + 2 * 1536)  // 9280
#define OFF_MBAR      (OFF_BHH + 192)                   // 9472 (8B aligned)
#define REC_SMEM_BYTES ((OFF_MBAR + 4) * 4)

__global__ void __cluster_dims__(4, 1, 1) __launch_bounds__(384, 1)
gru_rec_mma(const float* __restrict__ Whh, const float* __restrict__ bhh_g,
            const float* __restrict__ gi, float* __restrict__ hout,
            int store_all)
{
    extern __shared__ float smf[];
    float* bhh = smf + OFF_BHH;
    float* gh  = smf + OFF_GH;
    const uint32_t mbar = (uint32_t)__cvta_generic_to_shared(smf + OFF_MBAR);

    cg::cluster_group cluster = cg::this_cluster();
    const int rank = cluster.block_rank();
    const int B0   = (blockIdx.x >> 2) * 8;       // 8 batch rows per cluster

    const int t    = threadIdx.x;
    const int lane = t & 31;
    const int w    = t >> 5;              // 0..11
    const int gid  = lane >> 2;           // 0..7
    const int tig  = lane & 3;            // 0..3

    // ---- W_hh fragments -> registers (once): warp w owns m-tile w ----
    float wa0[32], wa1[32], wa2[32], wa3[32];
    {
        const int g  = w >> 2;
        const int r0 = g * 256 + rank * 64 + (w & 3) * 16 + gid;
        const float* p0 = Whh + (size_t)r0 * 256;
        const float* p1 = p0 + 8 * 256;
#pragma unroll
        for (int s = 0; s < 32; s++) {
            wa0[s] = f2tf32(p0[8 * s + tig]);
            wa1[s] = f2tf32(p1[8 * s + tig]);
            wa2[s] = f2tf32(p0[8 * s + tig + 4]);
            wa3[s] = f2tf32(p1[8 * s + tig + 4]);
        }
    }
    for (int i = t; i < 192; i += 384)
        bhh[i] = bhh_g[((i >> 6) << 8) + rank * 64 + (i & 63)];
    for (int i = t; i < 2 * 256 * HP; i += 384) smf[i] = 0.0f;   // zero hbufs
    if (t == 0) MBAR_INIT(mbar, 4);
    __syncthreads();
    cluster.sync();                         // mbar + zeroed hbufs visible
    if (t < 4) MBAR_ARRIVE_RANK(mbar, t);   // prime phase 0: h(0) "ready"

    // gate-phase identity (threads 0..255)
    const int j     = t & 63;
    const int bb    = (t >> 6) & 3;
    const int kglob = rank * 64 + j;
    float hprev0 = 0.0f, hprev1 = 0.0f;     // exact fp32 state

    // cp.async chunk identity (384 threads x 16B = 1536 floats = 8x192)
    const int cb   = t / 48;
    const int crem = t % 48;
    const int cg_  = crem >> 4;
    const int cq   = crem & 15;
    const uint32_t gis_dst0 = (uint32_t)__cvta_generic_to_shared(
        smf + OFF_GIS(0) + cb * 192 + cg_ * 64 + cq * 4);
    const float* gi_src0 = gi + ((size_t)B0 + cb) * G3 + cg_ * 256 + rank * 64 + cq * 4;

    // prologue: gi(0) into gi_s buffer 0
    cp_async16(gis_dst0, gi_src0);
    asm volatile("cp.async.commit_group;" ::: "memory");

    for (int ts = 0; ts < T_STEPS; ts++) {
        const int par = ts & 1;

        // prefetch gi(ts+1) into the other buffer (full step of cover)
        {
            const int tn = (ts + 1 < T_STEPS) ? (ts + 1) : ts;
            cp_async16(gis_dst0 + (par ^ 1) * 1536 * 4,
                       gi_src0 + (size_t)tn * BATCH * G3);
            asm volatile("cp.async.commit_group;" ::: "memory");
        }

        MBAR_WAIT(mbar, par);                          // h(ts) visible (all CTAs)

        // ---- GEMM: D[192x8] = W @ h^T, 4 independent chains (depth 8) ----
        {
            float c0[4] = {0, 0, 0, 0}, c1[4] = {0, 0, 0, 0};
            float c2[4] = {0, 0, 0, 0}, c3[4] = {0, 0, 0, 0};
            const float* hb = smf + OFF_HBUF(par) + tig * HP + gid;
#pragma unroll
            for (int s = 0; s < 32; s += 4) {
                float b0[2] = { hb[(s + 0) * 8 * HP], hb[(s + 0) * 8 * HP + 4 * HP] };
                float b1[2] = { hb[(s + 1) * 8 * HP], hb[(s + 1) * 8 * HP + 4 * HP] };
                float b2[2] = { hb[(s + 2) * 8 * HP], hb[(s + 2) * 8 * HP + 4 * HP] };
                float b3[2] = { hb[(s + 3) * 8 * HP], hb[(s + 3) * 8 * HP + 4 * HP] };
                float w0[4] = { wa0[s + 0], wa1[s + 0], wa2[s + 0], wa3[s + 0] };
                float w1[4] = { wa0[s + 1], wa1[s + 1], wa2[s + 1], wa3[s + 1] };
                float w2[4] = { wa0[s + 2], wa1[s + 2], wa2[s + 2], wa3[s + 2] };
                float w3[4] = { wa0[s + 3], wa1[s + 3], wa2[s + 3], wa3[s + 3] };
                mma_tf32(c0, w0, b0);
                mma_tf32(c1, w1, b1);
                mma_tf32(c2, w2, b2);
                mma_tf32(c3, w3, b3);
            }
            const int lr = w * 16 + gid;
            const int bi = tig * 2;
            gh[(bi    ) * 200 + lr    ] = (c0[0] + c1[0]) + (c2[0] + c3[0]);
            gh[(bi + 1) * 200 + lr    ] = (c0[1] + c1[1]) + (c2[1] + c3[1]);
            gh[(bi    ) * 200 + lr + 8] = (c0[2] + c1[2]) + (c2[2] + c3[2]);
            gh[(bi + 1) * 200 + lr + 8] = (c0[3] + c1[3]) + (c2[3] + c3[3]);
        }
        // per-thread wait for gi(ts) (gi(ts+1) may stay in flight), ALL threads,
        // BEFORE the barrier (v3c rule)
        asm volatile("cp.async.wait_group 1;" ::: "memory");
        __syncthreads();                               // gh + gi_s[par] ready

        // ---- gates + exact-register h update + tf32 DSMEM broadcast ----
        if (t < 256) {
            const float* gis = smf + OFF_GIS(par);
            float* hwr = smf + OFF_HBUF(par ^ 1);
            const float br = bhh[j], bz = bhh[64 + j], bn = bhh[128 + j];
#pragma unroll
            for (int i = 0; i < 2; i++) {
                const int b = bb + 4 * i;
                const float hr = gh[b * 200 + j]       + br;
                const float hz = gh[b * 200 + 64 + j]  + bz;
                const float hn = gh[b * 200 + 128 + j] + bn;
                const float ir  = gis[b * 192 + j];
                const float iz  = gis[b * 192 + 64 + j];
                const float in_ = gis[b * 192 + 128 + j];
                const float r = __fdividef(1.0f, 1.0f + __expf(-(ir + hr)));
                const float z = __fdividef(1.0f, 1.0f + __expf(-(iz + hz)));
                const float n = tanh_fast(in_ + r * hn);
                const float hprev = (i == 0) ? hprev0 : hprev1;
                const float hnew  = (1.0f - z) * n + z * hprev;
                if (i == 0) hprev0 = hnew; else hprev1 = hnew;

                const float hop = f2tf32(hnew);
                float* lp = hwr + kglob * HP + b;
#pragma unroll
                for (int q = 0; q < 4; q++)
                    *(float*)cluster.map_shared_rank(lp, q) = hop;

                if (store_all) {
                    hout[((size_t)ts * BATCH + B0 + b) * HID + kglob] = hnew;
                } else if (ts == T_STEPS - 1) {
                    hout[(size_t)(B0 + b) * HID + kglob] = hnew;
                }
            }
        }
        __syncthreads();                     // all gates stores issued CTA-wide
        if (t < 4) MBAR_ARRIVE_RANK(mbar, t);          // signal h(ts+1) ready
    }

    // REQUIRED: no CTA may exit while peers can still DSMEM-store into its
    // SMEM (final step's gates writes).
    cluster.sync();
}

// =============================================================================
// FC on the last hidden state
// =============================================================================
__global__ __launch_bounds__(256) void fc_kernel(
    const float* __restrict__ Wfc, const float* __restrict__ bfc,
    float* __restrict__ out)
{
    __shared__ float hs[256];
    const int b = blockIdx.x;
    const int o = threadIdx.x;
    hs[o] = g_h2[b * 256 + o];
    __syncthreads();
    const float* wr = Wfc + (size_t)o * 256;
    float acc = 0.0f;
#pragma unroll 8
    for (int k = 0; k < 256; k += 4) {
        const float4 wv = *(const float4*)(wr + k);
        acc += hs[k] * wv.x + hs[k + 1] * wv.y + hs[k + 2] * wv.z + hs[k + 3] * wv.w;
    }
    out[b * 256 + o] = acc + bfc[o];
}

// =============================================================================
extern "C" void kernel_launch(void* const* d_in, const int* in_sizes, int n_in,
                              void* d_out, int out_size)
{
    const float* x     = (const float*)d_in[0];
    const float* W_ih0 = (const float*)d_in[1];
    const float* W_hh0 = (const float*)d_in[2];
    const float* b_ih0 = (const float*)d_in[3];
    const float* b_hh0 = (const float*)d_in[4];
    const float* W_ih1 = (const float*)d_in[5];
    const float* W_hh1 = (const float*)d_in[6];
    const float* b_ih1 = (const float*)d_in[7];
    const float* b_hh1 = (const float*)d_in[8];
    const float* W_fc  = (const float*)d_in[9];
    const float* b_fc  = (const float*)d_in[10];
    float* out = (float*)d_out;

    float *gi_p, *h1_p, *h2_p;
    cudaGetSymbolAddress((void**)&gi_p, g_gi);
    cudaGetSymbolAddress((void**)&h1_p, g_h1);
    cudaGetSymbolAddress((void**)&h2_p, g_h2);

    cudaFuncSetAttribute(gru_rec_mma, cudaFuncAttributeMaxDynamicSharedMemorySize,
                         REC_SMEM_BYTES);

    const int M = T_STEPS * BATCH;        // 131072
    dim3 gemm_grid(G3 / 128, M / 128);    // (6, 1024)

    // layer 0: gi0 = x @ W_ih0^T + b_ih0   (tf32 HMMA, K=128)
    gemm_tf32mma<<<gemm_grid, 256>>>(x, W_ih0, b_ih0, gi_p, G3, IN0);
    // layer 0 recurrence -> g_h1[T,B,H]   (32 clusters x 4 CTAs, 8 batch each)
    gru_rec_mma<<<128, 384, REC_SMEM_BYTES>>>(W_hh0, b_hh0, gi_p, h1_p, 1);
    // layer 1: gi1 = h1 @ W_ih1^T + b_ih1  (tf32 HMMA, K=256)
    gemm_tf32mma<<<gemm_grid, 256>>>(h1_p, W_ih1, b_ih1, gi_p, G3, HID);
    // layer 1 recurrence -> g_h2[B,H]
    gru_rec_mma<<<128, 384, REC_SMEM_BYTES>>>(W_hh1, b_hh1, gi_p, h2_p, 0);
    // FC head
    fc_kernel<<<BATCH, 256>>>(W_fc, b_fc, out);
}